// round 14
// baseline (speedup 1.0000x reference)
#include <cuda_runtime.h>
#include <cuda_bf16.h>
#include <cstddef>

// NetAE batch-1 forward: HBM-bound GEMV chain (~596MB fp32 weights/call).
// Round 14 (base = r12 118.8us + r13's DE shuffle fix, early triggers reverted):
// Small stages fused via intra-kernel spin barriers (producer blocks set a
// counter after threadfence; consumer blocks spin, then proceed — consumers
// prefetch their weights into registers BEFORE the spin, so their HBM stream
// overlaps the producer inside one kernel):
//   gemv_AB    = A + B            (512 blocks)
//   gemv_FGout = F + G + out      (392 blocks)
// Chain: AB -> C -> DE -> FGout = 4 launches (was 7). Counters self-reset by
// the last consumer block each call -> graph-replay deterministic.

#define D_H    2048
#define D_A    256
#define N_EXP  16
#define D_OUT  512

__device__ float g_pA[128 * 2048];
__device__ float g_pB[128 * 2048];
__device__ float g_pC[16 * 32 * 2048];
__device__ float g_pDs[16 * 64];         // per-block k.q scalar partials
__device__ float g_pE[512 * 2048];       // UNSCALED V partials
__device__ float g_pF[128 * 2048];
__device__ float g_pG[256 * 512];
__device__ int   g_cntA, g_cntB, g_cntF, g_cntG, g_cntO;

__device__ __forceinline__ float4 f4add(float4 a, float4 b) {
    return make_float4(a.x + b.x, a.y + b.y, a.z + b.z, a.w + b.w);
}

// ---------------------------------------------------------------------------
// Shared prologue: build sx[RPS] = x-slice [i0, i0+RPS).
//   MODE 0: sx[r] = xsrc[i0+r]
//   MODE 1: sx[r] = [relu](biasx[bb*NPREV+i0+r] + sum_{s<SPREV} xsrc[(bb*SPREV+s)*NPREV+i0+r])
// ---------------------------------------------------------------------------
template<int BLK, int RPS, int MODE, int SPREV, int NPREV, bool RELU_X, bool PREV_PER_B>
__device__ __forceinline__
void stage_x(float* sx, const float* __restrict__ xsrc,
             const float* __restrict__ biasx, int i0, int b)
{
    const int tid = threadIdx.x;
    if constexpr (MODE == 0) {
        for (int r = tid; r < RPS; r += BLK) sx[r] = xsrc[i0 + r];
        __syncthreads();
    } else {
        constexpr int NQ = RPS / 4;
        constexpr int CH = BLK / NQ;
        __shared__ float4 sxp4[BLK];
        const int q = tid % NQ;
        const int c = tid / NQ;
        const int bb = PREV_PER_B ? b : 0;
        const float4* p = reinterpret_cast<const float4*>(
            xsrc + ((size_t)bb * SPREV) * NPREV + i0);
        float4 v = make_float4(0.f, 0.f, 0.f, 0.f);
        #pragma unroll
        for (int s = c; s < SPREV; s += CH)
            v = f4add(v, p[(size_t)s * (NPREV / 4) + q]);
        sxp4[tid] = v;
        __syncthreads();
        if (tid < NQ) {
            float4 v2 = reinterpret_cast<const float4*>(
                            biasx + (size_t)bb * NPREV + i0)[tid];
            #pragma unroll
            for (int cc = 0; cc < CH; cc++) v2 = f4add(v2, sxp4[tid + cc * NQ]);
            if constexpr (RELU_X) {
                v2.x = fmaxf(v2.x, 0.f); v2.y = fmaxf(v2.y, 0.f);
                v2.z = fmaxf(v2.z, 0.f); v2.w = fmaxf(v2.w, 0.f);
            }
            reinterpret_cast<float4*>(sx)[tid] = v2;
        }
        __syncthreads();
    }
}

__device__ __forceinline__ void spin_until(int* cnt, int target) {
    if (threadIdx.x == 0) {
        while (atomicAdd(cnt, 0) < target) __nanosleep(64);
    }
    __syncthreads();
    __threadfence();
}

__device__ __forceinline__ void signal_done(int* cnt) {
    __threadfence();
    __syncthreads();
    if (threadIdx.x == 0) atomicAdd(cnt, 1);
}

// ---------------------------------------------------------------------------
// Fused A+B. 512 blocks x 256 thr.
//   bid <  256: A — pA[slice*2048+j] = splitK(x @ W1), signal cntA
//   bid >= 256: B — prefetch W2 into regs, spin cntA==256, h1 fused prologue,
//               pB[slice*2048+j] = splitK(h1 @ W2); last B block resets counters.
// ---------------------------------------------------------------------------
__global__ __launch_bounds__(256)
void gemv_AB(const float* __restrict__ W1, const float* __restrict__ x,
             const float* __restrict__ W2, const float* __restrict__ b1,
             float* __restrict__ pA, float* __restrict__ pB)
{
    const int tid = threadIdx.x;
    const int bid = blockIdx.x;
    if (bid < 256) {
        __shared__ float sx[16];
        const int xp = bid & 1, slice = bid >> 1;
        const int i0 = slice * 16;
        const int j  = (xp * 256 + tid) * 4;
        const float* Wp = W1 + (size_t)i0 * 2048 + j;
        float4 wreg[16];
        #pragma unroll
        for (int rr = 0; rr < 16; rr++)
            wreg[rr] = *reinterpret_cast<const float4*>(Wp + (size_t)rr * 2048);
        cudaGridDependencySynchronize();
        if (tid < 16) sx[tid] = x[i0 + tid];
        __syncthreads();
        float4 acc = make_float4(0.f, 0.f, 0.f, 0.f);
        #pragma unroll
        for (int rr = 0; rr < 16; rr++) {
            const float xi = sx[rr];
            acc.x += xi * wreg[rr].x; acc.y += xi * wreg[rr].y;
            acc.z += xi * wreg[rr].z; acc.w += xi * wreg[rr].w;
        }
        *reinterpret_cast<float4*>(pA + (size_t)slice * 2048 + j) = acc;
        signal_done(&g_cntA);
    } else {
        __shared__ float sx[16];
        const int b2 = bid - 256;
        const int xp = b2 & 1, slice = b2 >> 1;
        const int i0 = slice * 16;
        const int j  = (xp * 256 + tid) * 4;
        const float* Wp = W2 + (size_t)i0 * 2048 + j;
        float4 wreg[16];
        #pragma unroll
        for (int rr = 0; rr < 16; rr++)
            wreg[rr] = *reinterpret_cast<const float4*>(Wp + (size_t)rr * 2048);
        cudaGridDependencySynchronize();
        spin_until(&g_cntA, 256);
        stage_x<256, 16, 1, 128, 2048, true, false>(sx, pA, b1, i0, 0);
        float4 acc = make_float4(0.f, 0.f, 0.f, 0.f);
        #pragma unroll
        for (int rr = 0; rr < 16; rr++) {
            const float xi = sx[rr];
            acc.x += xi * wreg[rr].x; acc.y += xi * wreg[rr].y;
            acc.z += xi * wreg[rr].z; acc.w += xi * wreg[rr].w;
        }
        *reinterpret_cast<float4*>(pB + (size_t)slice * 2048 + j) = acc;
        __syncthreads();
        if (tid == 0) {
            const int v = atomicAdd(&g_cntB, 1);
            if (v == 255) { g_cntA = 0; g_cntB = 0; __threadfence(); }
        }
    }
}

// Generic split-K GEMV stage (used for C only now).
template<int BLK, int RPS, int N, int GRP, int MODE, int SPREV, int NPREV,
         bool RELU_X, bool PREV_PER_B, int PF>
__global__ __launch_bounds__(BLK)
void gemv_k(const float* __restrict__ W,
            const float* __restrict__ xsrc,
            const float* __restrict__ biasx,
            float* __restrict__ partOut)
{
    __shared__ float sx[RPS];
    const int tid   = threadIdx.x;
    const int slice = blockIdx.y;
    const int b     = blockIdx.z;
    const int S     = gridDim.y;
    const int i0    = slice * RPS;
    const int K     = S * RPS;

    constexpr int CT  = BLK / GRP;
    constexpr int RPG = RPS / GRP;
    const int g  = tid / CT;
    const int j  = (blockIdx.x * CT + (tid % CT)) * 4;
    const int r0 = g * RPG;
    const float* Wp = W + (size_t)b * K * N + (size_t)(i0 + r0) * N + j;

    float4 wreg[PF > 0 ? PF : 1];
    #pragma unroll
    for (int rr = 0; rr < PF; rr++)
        wreg[rr] = *reinterpret_cast<const float4*>(Wp + (size_t)rr * N);

    cudaGridDependencySynchronize();

    stage_x<BLK, RPS, MODE, SPREV, NPREV, RELU_X, PREV_PER_B>(sx, xsrc, biasx, i0, b);

    float4 acc = make_float4(0.f, 0.f, 0.f, 0.f);
    #pragma unroll
    for (int rr = 0; rr < PF; rr++) {
        const float xi = sx[r0 + rr];
        acc.x += xi * wreg[rr].x; acc.y += xi * wreg[rr].y;
        acc.z += xi * wreg[rr].z; acc.w += xi * wreg[rr].w;
    }
    #pragma unroll 16
    for (int rr = PF; rr < RPG; rr++) {
        const float4 w = *reinterpret_cast<const float4*>(Wp + (size_t)rr * N);
        const float xi = sx[r0 + rr];
        acc.x += xi * w.x; acc.y += xi * w.y;
        acc.z += xi * w.z; acc.w += xi * w.w;
    }
    *reinterpret_cast<float4*>(
        partOut + ((size_t)((b * S + slice) * GRP + g)) * N + j) = acc;
    cudaTriggerProgrammaticLaunchCompletion();
}

// ---------------------------------------------------------------------------
// Merged D+E stage, uniform 1024 blocks. grid = (2, 32, 16). End trigger.
// D-tile dots its k-partial with q in-kernel -> one scalar per block (pDs).
// ---------------------------------------------------------------------------
__global__ __launch_bounds__(256)
void gemv_DE(const float* __restrict__ Wv, const float* __restrict__ Wk,
             const float* __restrict__ pC, const float* __restrict__ b_exp,
             const float* __restrict__ W_q, const float* __restrict__ b_q,
             const int* __restrict__ task_id,
             float* __restrict__ pE, float* __restrict__ pDs)
{
    __shared__ float sx[64];
    __shared__ float redD[8];
    const int tid   = threadIdx.x;
    const int xp    = blockIdx.x;
    const int slice = blockIdx.y;
    const int b     = blockIdx.z;
    const int i0    = slice * 64;

    cudaGridDependencySynchronize();
    stage_x<256, 64, 1, 32, 2048, true, true>(sx, pC, b_exp, i0, b);

    // ---- E tile ----
    {
        const int j = (xp * 256 + tid) * 4;
        const float* Wp = Wv + (size_t)b * 2048 * 2048 + (size_t)i0 * 2048 + j;
        float4 acc = make_float4(0.f, 0.f, 0.f, 0.f);
        #pragma unroll 16
        for (int rr = 0; rr < 64; rr++) {
            const float4 w = *reinterpret_cast<const float4*>(Wp + (size_t)rr * 2048);
            const float xi = sx[rr];
            acc.x += xi * w.x; acc.y += xi * w.y;
            acc.z += xi * w.z; acc.w += xi * w.w;
        }
        *reinterpret_cast<float4*>(pE + ((size_t)(b * 32 + slice)) * 2048 + j) = acc;
    }
    // ---- D tile -> scalar k.q partial (warp-shuffle reduce) ----
    {
        const int g  = tid / 32;
        const int jd = xp * 128 + (tid % 32) * 4;
        const int r0 = g * 8;
        const float* Wp = Wk + (size_t)b * 2048 * 256 + (size_t)(i0 + r0) * 256 + jd;
        float4 acc = make_float4(0.f, 0.f, 0.f, 0.f);
        #pragma unroll
        for (int rr = 0; rr < 8; rr++) {
            const float4 w = *reinterpret_cast<const float4*>(Wp + (size_t)rr * 256);
            const float xi = sx[r0 + rr];
            acc.x += xi * w.x; acc.y += xi * w.y;
            acc.z += xi * w.z; acc.w += xi * w.w;
        }
        const int t = *task_id;
        const float4 wq = *reinterpret_cast<const float4*>(
            W_q + ((size_t)t * 10 + t) * D_A + jd);
        const float4 bq = *reinterpret_cast<const float4*>(b_q + t * D_A + jd);
        float s = acc.x * (wq.x + bq.x) + acc.y * (wq.y + bq.y)
                + acc.z * (wq.z + bq.z) + acc.w * (wq.w + bq.w);
        #pragma unroll
        for (int off = 16; off; off >>= 1) s += __shfl_xor_sync(0xFFFFFFFFu, s, off);
        if ((tid & 31) == 0) redD[g] = s;
        __syncthreads();
        if (tid == 0) {
            pDs[b * 64 + slice * 2 + xp] =
                redD[0] + redD[1] + redD[2] + redD[3]
              + redD[4] + redD[5] + redD[6] + redD[7];
        }
    }
}

// ---------------------------------------------------------------------------
// Fused F + G + out. 392 blocks x 256 thr.
//   bid <  256: F — ekq from pDs + b_k.q, MODE-2 staging over pE, GEMV vs W_t
//   bid <  384: G — prefetch W_l, spin cntF, h-t fused prologue, GEMV
//   bid >= 384: out — spin cntG, reduce pG + b_l
// ---------------------------------------------------------------------------
__global__ __launch_bounds__(256)
void gemv_FGout(const float* __restrict__ W_t, const float* __restrict__ pE,
                const float* __restrict__ pDs, const float* __restrict__ b_k,
                const float* __restrict__ W_q, const float* __restrict__ b_q,
                const float* __restrict__ b_v, const int* __restrict__ task_id,
                float* __restrict__ pF,
                const float* __restrict__ W_l, const float* __restrict__ b_t,
                float* __restrict__ pG,
                const float* __restrict__ b_l, float* __restrict__ out)
{
    const int tid = threadIdx.x;
    const int bid = blockIdx.x;

    if (bid < 256) {                                    // ---- F ----
        __shared__ float sekq[16];
        __shared__ float tmp[256];
        __shared__ float4 sxp4f[256];
        __shared__ float sxf[16];
        const int xp = bid & 1, slice = bid >> 1;
        const int i0 = slice * 16;
        const int j  = (xp * 256 + tid) * 4;
        const float* Wp = W_t + (size_t)i0 * 2048 + j;
        float4 wreg[16];
        #pragma unroll
        for (int rr = 0; rr < 16; rr++)
            wreg[rr] = *reinterpret_cast<const float4*>(Wp + (size_t)rr * 2048);

        cudaGridDependencySynchronize();

        // ekq[n] = sum_{i<64} pDs[n*64+i] + dot(b_k[n], q)
        {
            const int t = *task_id;
            const int n = tid >> 4;
            const int l = tid & 15;
            float s = 0.f;
            #pragma unroll
            for (int k = 0; k < 16; k++) {
                const int a = l * 16 + k;
                const float qv = W_q[((size_t)t * 10 + t) * D_A + a] + b_q[t * D_A + a];
                s += b_k[n * D_A + a] * qv;
            }
            tmp[tid] = s;
            __syncthreads();
            if (tid < 16) {
                float v = 0.f;
                #pragma unroll
                for (int l2 = 0; l2 < 16; l2++) v += tmp[tid * 16 + l2];
                #pragma unroll
                for (int i = 0; i < 64; i++) v += pDs[tid * 64 + i];
                sekq[tid] = v;
            }
            __syncthreads();
        }
        // MODE-2 staging: sxf[16] = ekq-weighted reduce of 512 pE rows + ekq.b_v
        {
            const int q4 = tid % 4;
            const int c  = tid / 4;
            const float4* p = reinterpret_cast<const float4*>(pE + i0);
            float4 v = make_float4(0.f, 0.f, 0.f, 0.f);
            #pragma unroll
            for (int s = c; s < 512; s += 64) {
                float4 w = p[(size_t)s * 512 + q4];
                const float sc = sekq[s >> 5];
                v.x += sc * w.x; v.y += sc * w.y;
                v.z += sc * w.z; v.w += sc * w.w;
            }
            sxp4f[tid] = v;
            __syncthreads();
            if (tid < 4) {
                float4 v2 = make_float4(0.f, 0.f, 0.f, 0.f);
                #pragma unroll
                for (int cc = 0; cc < 64; cc++) v2 = f4add(v2, sxp4f[tid + cc * 4]);
                #pragma unroll
                for (int n = 0; n < N_EXP; n++) {
                    const float4 bq = reinterpret_cast<const float4*>(
                        b_v + (size_t)n * 2048 + i0)[tid];
                    const float e = sekq[n];
                    v2.x += e * bq.x; v2.y += e * bq.y;
                    v2.z += e * bq.z; v2.w += e * bq.w;
                }
                reinterpret_cast<float4*>(sxf)[tid] = v2;
            }
            __syncthreads();
        }
        float4 acc = make_float4(0.f, 0.f, 0.f, 0.f);
        #pragma unroll
        for (int rr = 0; rr < 16; rr++) {
            const float xi = sxf[rr];
            acc.x += xi * wreg[rr].x; acc.y += xi * wreg[rr].y;
            acc.z += xi * wreg[rr].z; acc.w += xi * wreg[rr].w;
        }
        *reinterpret_cast<float4*>(pF + (size_t)slice * 2048 + j) = acc;
        signal_done(&g_cntF);

    } else if (bid < 384) {                             // ---- G ----
        __shared__ float sxg[16];
        const int gid = bid - 256;                      // slice in [0,128)
        const int i0  = gid * 16;
        const int g   = tid / 128;                      // GRP=2
        const int j   = (tid % 128) * 4;
        const int r0  = g * 8;
        const float* Wp = W_l + (size_t)(i0 + r0) * 512 + j;
        float4 wreg[8];
        #pragma unroll
        for (int rr = 0; rr < 8; rr++)
            wreg[rr] = *reinterpret_cast<const float4*>(Wp + (size_t)rr * 512);

        cudaGridDependencySynchronize();
        spin_until(&g_cntF, 256);
        stage_x<256, 16, 1, 128, 2048, true, false>(sxg, pF, b_t, i0, 0);

        float4 acc = make_float4(0.f, 0.f, 0.f, 0.f);
        #pragma unroll
        for (int rr = 0; rr < 8; rr++) {
            const float xi = sxg[r0 + rr];
            acc.x += xi * wreg[rr].x; acc.y += xi * wreg[rr].y;
            acc.z += xi * wreg[rr].z; acc.w += xi * wreg[rr].w;
        }
        *reinterpret_cast<float4*>(pG + ((size_t)(gid * 2 + g)) * 512 + j) = acc;
        signal_done(&g_cntG);

    } else {                                            // ---- out ----
        __shared__ float4 red4[256];
        const int oid = bid - 384;
        const int ql = tid % 16;
        const int c  = tid / 16;
        const int jq = oid * 16 + ql;
        cudaGridDependencySynchronize();
        spin_until(&g_cntG, 128);
        const float4* p = reinterpret_cast<const float4*>(pG);
        float4 acc = make_float4(0.f, 0.f, 0.f, 0.f);
        #pragma unroll 8
        for (int s = c; s < 256; s += 16) acc = f4add(acc, p[(size_t)s * 128 + jq]);
        red4[tid] = acc;
        __syncthreads();
        #pragma unroll
        for (int off = 8; off >= 1; off >>= 1) {
            if (c < off) red4[tid] = f4add(red4[tid], red4[tid + off * 16]);
            __syncthreads();
        }
        if (c == 0) {
            float4 v = f4add(red4[ql], reinterpret_cast<const float4*>(b_l)[jq]);
            reinterpret_cast<float4*>(out)[jq] = v;
        }
        __syncthreads();
        if (tid == 0) {
            const int v = atomicAdd(&g_cntO, 1);
            if (v == 7) { g_cntF = 0; g_cntG = 0; g_cntO = 0; __threadfence(); }
        }
    }
}

// ---------------------------------------------------------------------------
template<typename K, typename... A>
static inline void launch_pdl(K kern, dim3 g, dim3 b, A... args)
{
    cudaLaunchConfig_t cfg = {};
    cfg.gridDim = g;
    cfg.blockDim = b;
    cfg.stream = 0;
    cudaLaunchAttribute at[1];
    at[0].id = cudaLaunchAttributeProgrammaticStreamSerialization;
    at[0].val.programmaticStreamSerializationAllowed = 1;
    cfg.attrs = at;
    cfg.numAttrs = 1;
    cudaLaunchKernelEx(&cfg, kern, args...);
}

extern "C" void kernel_launch(void* const* d_in, const int* in_sizes, int n_in,
                              void* d_out, int out_size)
{
    const float* x     = (const float*)d_in[0];
    const float* W1    = (const float*)d_in[1];
    const float* b1    = (const float*)d_in[2];
    const float* W2    = (const float*)d_in[3];
    const float* b2    = (const float*)d_in[4];
    const float* W_exp = (const float*)d_in[5];
    const float* b_exp = (const float*)d_in[6];
    const float* W_v   = (const float*)d_in[7];
    const float* b_v   = (const float*)d_in[8];
    const float* W_k   = (const float*)d_in[9];
    const float* b_k   = (const float*)d_in[10];
    const float* W_q   = (const float*)d_in[11];
    const float* b_q   = (const float*)d_in[12];
    const float* W_t   = (const float*)d_in[13];
    const float* b_t   = (const float*)d_in[14];
    const float* W_l   = (const float*)d_in[15];
    const float* b_l   = (const float*)d_in[16];
    const int*   tid   = (const int*)d_in[17];
    float* out = (float*)d_out;

    float *pA, *pB, *pC, *pDs, *pE, *pF, *pG;
    cudaGetSymbolAddress((void**)&pA, g_pA);
    cudaGetSymbolAddress((void**)&pB, g_pB);
    cudaGetSymbolAddress((void**)&pC, g_pC);
    cudaGetSymbolAddress((void**)&pDs, g_pDs);
    cudaGetSymbolAddress((void**)&pE, g_pE);
    cudaGetSymbolAddress((void**)&pF, g_pF);
    cudaGetSymbolAddress((void**)&pG, g_pG);

    // A+B fused (spin barrier inside)   32MB, 512 blocks
    launch_pdl(gemv_AB, dim3(512), dim3(256), W1, x, W2, b1, pA, pB);
    // C: h2 fused; pC[n] = splitK(h2 @ W_exp[n])   256MB, 1024 blocks
    launch_pdl(gemv_k<256, 64, 2048, 1, 1, 128, 2048, true, false, 0>,
               dim3(2, 32, 16), dim3(256), W_exp, pB, b2, pC);
    // D+E merged + in-kernel k.q dot      288MB, uniform 1024 blocks
    launch_pdl(gemv_DE, dim3(2, 32, 16), dim3(256),
               W_v, W_k, pC, b_exp, W_q, b_q, tid, pE, pDs);
    // F+G+out fused (two spin barriers)   20MB, 392 blocks
    launch_pdl(gemv_FGout, dim3(392), dim3(256),
               W_t, pE, pDs, b_k, W_q, b_q, b_v, tid, pF,
               W_l, b_t, pG, b_l, out);
}

// round 15
// speedup vs baseline: 1.0207x; 1.0207x over previous
#include <cuda_runtime.h>
#include <cuda_bf16.h>
#include <cstddef>

// NetAE batch-1 forward: HBM-bound GEMV chain (~596MB fp32 weights/call).
// Round 15 = round 12 (measured best structure, 118.8us) + exactly ONE change:
// DE's D-dot reduction uses warp shuffle + a single __syncthreads (r13's fix,
// measured DE 51.7 -> 49.1us) instead of the 3-sync smem tree. All PDL
// triggers at kernel end (early triggers measured as regressions in r9/r13;
// intra-kernel spin fusion measured as regression in r14 via register
// fattening to 116 regs / 24% occ).

#define D_H    2048
#define D_A    256
#define N_EXP  16
#define D_OUT  512

__device__ float g_pA[128 * 2048];
__device__ float g_pB[128 * 2048];
__device__ float g_pC[16 * 32 * 2048];
__device__ float g_pDs[16 * 64];         // per-block k.q scalar partials
__device__ float g_pE[512 * 2048];       // UNSCALED V partials
__device__ float g_pF[128 * 2048];
__device__ float g_pG[256 * 512];

__device__ __forceinline__ float4 f4add(float4 a, float4 b) {
    return make_float4(a.x + b.x, a.y + b.y, a.z + b.z, a.w + b.w);
}

// ---------------------------------------------------------------------------
// Shared prologue: build sx[RPS] = x-slice [i0, i0+RPS).
//   MODE 0: sx[r] = xsrc[i0+r]
//   MODE 1: sx[r] = [relu](biasx[bb*NPREV+i0+r] + sum_{s<SPREV} xsrc[(bb*SPREV+s)*NPREV+i0+r])
// ---------------------------------------------------------------------------
template<int BLK, int RPS, int MODE, int SPREV, int NPREV, bool RELU_X, bool PREV_PER_B>
__device__ __forceinline__
void stage_x(float* sx, const float* __restrict__ xsrc,
             const float* __restrict__ biasx, int i0, int b)
{
    const int tid = threadIdx.x;
    if constexpr (MODE == 0) {
        for (int r = tid; r < RPS; r += BLK) sx[r] = xsrc[i0 + r];
        __syncthreads();
    } else {
        constexpr int NQ = RPS / 4;
        constexpr int CH = BLK / NQ;
        __shared__ float4 sxp4[BLK];
        const int q = tid % NQ;
        const int c = tid / NQ;
        const int bb = PREV_PER_B ? b : 0;
        const float4* p = reinterpret_cast<const float4*>(
            xsrc + ((size_t)bb * SPREV) * NPREV + i0);
        float4 v = make_float4(0.f, 0.f, 0.f, 0.f);
        #pragma unroll
        for (int s = c; s < SPREV; s += CH)
            v = f4add(v, p[(size_t)s * (NPREV / 4) + q]);
        sxp4[tid] = v;
        __syncthreads();
        if (tid < NQ) {
            float4 v2 = reinterpret_cast<const float4*>(
                            biasx + (size_t)bb * NPREV + i0)[tid];
            #pragma unroll
            for (int cc = 0; cc < CH; cc++) v2 = f4add(v2, sxp4[tid + cc * NQ]);
            if constexpr (RELU_X) {
                v2.x = fmaxf(v2.x, 0.f); v2.y = fmaxf(v2.y, 0.f);
                v2.z = fmaxf(v2.z, 0.f); v2.w = fmaxf(v2.w, 0.f);
            }
            reinterpret_cast<float4*>(sx)[tid] = v2;
        }
        __syncthreads();
    }
}

// Generic split-K GEMV stage. PF = rows prefetched into regs before the wait.
template<int BLK, int RPS, int N, int GRP, int MODE, int SPREV, int NPREV,
         bool RELU_X, bool PREV_PER_B, int PF>
__global__ __launch_bounds__(BLK)
void gemv_k(const float* __restrict__ W,
            const float* __restrict__ xsrc,
            const float* __restrict__ biasx,
            float* __restrict__ partOut)
{
    __shared__ float sx[RPS];
    const int tid   = threadIdx.x;
    const int slice = blockIdx.y;
    const int b     = blockIdx.z;
    const int S     = gridDim.y;
    const int i0    = slice * RPS;
    const int K     = S * RPS;

    constexpr int CT  = BLK / GRP;
    constexpr int RPG = RPS / GRP;
    const int g  = tid / CT;
    const int j  = (blockIdx.x * CT + (tid % CT)) * 4;
    const int r0 = g * RPG;
    const float* Wp = W + (size_t)b * K * N + (size_t)(i0 + r0) * N + j;

    float4 wreg[PF > 0 ? PF : 1];
    #pragma unroll
    for (int rr = 0; rr < PF; rr++)
        wreg[rr] = *reinterpret_cast<const float4*>(Wp + (size_t)rr * N);

    cudaGridDependencySynchronize();

    stage_x<BLK, RPS, MODE, SPREV, NPREV, RELU_X, PREV_PER_B>(sx, xsrc, biasx, i0, b);

    float4 acc = make_float4(0.f, 0.f, 0.f, 0.f);
    #pragma unroll
    for (int rr = 0; rr < PF; rr++) {
        const float xi = sx[r0 + rr];
        acc.x += xi * wreg[rr].x; acc.y += xi * wreg[rr].y;
        acc.z += xi * wreg[rr].z; acc.w += xi * wreg[rr].w;
    }
    #pragma unroll 16
    for (int rr = PF; rr < RPG; rr++) {
        const float4 w = *reinterpret_cast<const float4*>(Wp + (size_t)rr * N);
        const float xi = sx[r0 + rr];
        acc.x += xi * w.x; acc.y += xi * w.y;
        acc.z += xi * w.z; acc.w += xi * w.w;
    }
    *reinterpret_cast<float4*>(
        partOut + ((size_t)((b * S + slice) * GRP + g)) * N + j) = acc;
    cudaTriggerProgrammaticLaunchCompletion();
}

// ---------------------------------------------------------------------------
// Merged D+E stage, uniform 1024 blocks. grid = (2, 32, 16).
// D-tile dots its k-partial with q in-kernel -> one scalar per block (pDs),
// reduced via warp shuffle + one __syncthreads.
// ---------------------------------------------------------------------------
__global__ __launch_bounds__(256)
void gemv_DE(const float* __restrict__ Wv, const float* __restrict__ Wk,
             const float* __restrict__ pC, const float* __restrict__ b_exp,
             const float* __restrict__ W_q, const float* __restrict__ b_q,
             const int* __restrict__ task_id,
             float* __restrict__ pE, float* __restrict__ pDs)
{
    __shared__ float sx[64];
    __shared__ float redD[8];
    const int tid   = threadIdx.x;
    const int xp    = blockIdx.x;
    const int slice = blockIdx.y;
    const int b     = blockIdx.z;
    const int i0    = slice * 64;

    cudaGridDependencySynchronize();
    stage_x<256, 64, 1, 32, 2048, true, true>(sx, pC, b_exp, i0, b);

    // ---- E tile ----
    {
        const int j = (xp * 256 + tid) * 4;
        const float* Wp = Wv + (size_t)b * 2048 * 2048 + (size_t)i0 * 2048 + j;
        float4 acc = make_float4(0.f, 0.f, 0.f, 0.f);
        #pragma unroll 16
        for (int rr = 0; rr < 64; rr++) {
            const float4 w = *reinterpret_cast<const float4*>(Wp + (size_t)rr * 2048);
            const float xi = sx[rr];
            acc.x += xi * w.x; acc.y += xi * w.y;
            acc.z += xi * w.z; acc.w += xi * w.w;
        }
        *reinterpret_cast<float4*>(pE + ((size_t)(b * 32 + slice)) * 2048 + j) = acc;
    }
    // ---- D tile -> scalar k.q partial (warp-shuffle reduce) ----
    {
        const int g  = tid / 32;
        const int jd = xp * 128 + (tid % 32) * 4;
        const int r0 = g * 8;
        const float* Wp = Wk + (size_t)b * 2048 * 256 + (size_t)(i0 + r0) * 256 + jd;
        float4 acc = make_float4(0.f, 0.f, 0.f, 0.f);
        #pragma unroll
        for (int rr = 0; rr < 8; rr++) {
            const float4 w = *reinterpret_cast<const float4*>(Wp + (size_t)rr * 256);
            const float xi = sx[r0 + rr];
            acc.x += xi * w.x; acc.y += xi * w.y;
            acc.z += xi * w.z; acc.w += xi * w.w;
        }
        const int t = *task_id;
        const float4 wq = *reinterpret_cast<const float4*>(
            W_q + ((size_t)t * 10 + t) * D_A + jd);
        const float4 bq = *reinterpret_cast<const float4*>(b_q + t * D_A + jd);
        float s = acc.x * (wq.x + bq.x) + acc.y * (wq.y + bq.y)
                + acc.z * (wq.z + bq.z) + acc.w * (wq.w + bq.w);
        #pragma unroll
        for (int off = 16; off; off >>= 1) s += __shfl_xor_sync(0xFFFFFFFFu, s, off);
        if ((tid & 31) == 0) redD[g] = s;
        __syncthreads();
        if (tid == 0) {
            pDs[b * 64 + slice * 2 + xp] =
                redD[0] + redD[1] + redD[2] + redD[3]
              + redD[4] + redD[5] + redD[6] + redD[7];
        }
    }
    cudaTriggerProgrammaticLaunchCompletion();
}

// ---------------------------------------------------------------------------
// F stage: prologue reconstructs ekq[16] from pDs + b_k.q, then MODE-2
// staging (ekq-weighted reduce of pE + ekq.b_v), then GEMV vs W_t with full
// register prefetch. grid(2,128), 256 thr, RPS=16.
// ---------------------------------------------------------------------------
__global__ __launch_bounds__(256)
void gemv_F(const float* __restrict__ W_t, const float* __restrict__ pE,
            const float* __restrict__ pDs, const float* __restrict__ b_k,
            const float* __restrict__ W_q, const float* __restrict__ b_q,
            const float* __restrict__ b_v, const int* __restrict__ task_id,
            float* __restrict__ pF)
{
    __shared__ float sekq[16];
    __shared__ float tmp[256];
    __shared__ float4 sxp4[256];
    __shared__ float sx[16];
    const int tid = threadIdx.x;
    const int slice = blockIdx.y;
    const int i0 = slice * 16;
    const int j  = (blockIdx.x * 256 + tid) * 4;
    const float* Wp = W_t + (size_t)i0 * 2048 + j;

    float4 wreg[16];
    #pragma unroll
    for (int rr = 0; rr < 16; rr++)
        wreg[rr] = *reinterpret_cast<const float4*>(Wp + (size_t)rr * 2048);

    cudaGridDependencySynchronize();

    // ekq[n] = sum_{i<64} pDs[n*64+i] + dot(b_k[n], q)
    {
        const int t = *task_id;
        const int n = tid >> 4;
        const int l = tid & 15;
        float s = 0.f;
        #pragma unroll
        for (int k = 0; k < 16; k++) {
            const int a = l * 16 + k;
            const float qv = W_q[((size_t)t * 10 + t) * D_A + a] + b_q[t * D_A + a];
            s += b_k[n * D_A + a] * qv;
        }
        tmp[tid] = s;
        __syncthreads();
        if (tid < 16) {
            float v = 0.f;
            #pragma unroll
            for (int l2 = 0; l2 < 16; l2++) v += tmp[tid * 16 + l2];
            #pragma unroll
            for (int i = 0; i < 64; i++) v += pDs[tid * 64 + i];
            sekq[tid] = v;
        }
        __syncthreads();
    }

    // MODE-2 staging: sx[16] = ekq-weighted reduce of 512 pE rows + ekq.b_v
    {
        const int q4 = tid % 4;
        const int c  = tid / 4;
        const float4* p = reinterpret_cast<const float4*>(pE + i0);
        float4 v = make_float4(0.f, 0.f, 0.f, 0.f);
        #pragma unroll
        for (int s = c; s < 512; s += 64) {
            float4 w = p[(size_t)s * 512 + q4];
            const float sc = sekq[s >> 5];
            v.x += sc * w.x; v.y += sc * w.y;
            v.z += sc * w.z; v.w += sc * w.w;
        }
        sxp4[tid] = v;
        __syncthreads();
        if (tid < 4) {
            float4 v2 = make_float4(0.f, 0.f, 0.f, 0.f);
            #pragma unroll
            for (int cc = 0; cc < 64; cc++) v2 = f4add(v2, sxp4[tid + cc * 4]);
            #pragma unroll
            for (int n = 0; n < N_EXP; n++) {
                const float4 bq = reinterpret_cast<const float4*>(
                    b_v + (size_t)n * 2048 + i0)[tid];
                const float e = sekq[n];
                v2.x += e * bq.x; v2.y += e * bq.y;
                v2.z += e * bq.z; v2.w += e * bq.w;
            }
            reinterpret_cast<float4*>(sx)[tid] = v2;
        }
        __syncthreads();
    }

    float4 acc = make_float4(0.f, 0.f, 0.f, 0.f);
    #pragma unroll
    for (int rr = 0; rr < 16; rr++) {
        const float xi = sx[rr];
        acc.x += xi * wreg[rr].x; acc.y += xi * wreg[rr].y;
        acc.z += xi * wreg[rr].z; acc.w += xi * wreg[rr].w;
    }
    *reinterpret_cast<float4*>(pF + ((size_t)slice) * 2048 + j) = acc;
    cudaTriggerProgrammaticLaunchCompletion();
}

// out[j] = b_l[j] + reduce_{s<256} pG[s*512 + j];  8 blocks x 256 thr.
__global__ __launch_bounds__(256)
void fin_out(const float* __restrict__ part,
             const float* __restrict__ b_l,
             float* __restrict__ out)
{
    __shared__ float4 red4[256];
    const int ql = threadIdx.x % 16;
    const int c  = threadIdx.x / 16;
    const int jq = blockIdx.x * 16 + ql;
    cudaGridDependencySynchronize();
    const float4* p = reinterpret_cast<const float4*>(part);
    float4 acc = make_float4(0.f, 0.f, 0.f, 0.f);
    #pragma unroll 8
    for (int s = c; s < 256; s += 16) acc = f4add(acc, p[(size_t)s * 128 + jq]);
    red4[threadIdx.x] = acc;
    __syncthreads();
    #pragma unroll
    for (int off = 8; off >= 1; off >>= 1) {
        if (c < off) red4[threadIdx.x] = f4add(red4[threadIdx.x],
                                               red4[threadIdx.x + off * 16]);
        __syncthreads();
    }
    if (c == 0) {
        float4 v = f4add(red4[ql], reinterpret_cast<const float4*>(b_l)[jq]);
        reinterpret_cast<float4*>(out)[jq] = v;
    }
    cudaTriggerProgrammaticLaunchCompletion();
}

// ---------------------------------------------------------------------------
template<typename K, typename... A>
static inline void launch_pdl(K kern, dim3 g, dim3 b, A... args)
{
    cudaLaunchConfig_t cfg = {};
    cfg.gridDim = g;
    cfg.blockDim = b;
    cfg.stream = 0;
    cudaLaunchAttribute at[1];
    at[0].id = cudaLaunchAttributeProgrammaticStreamSerialization;
    at[0].val.programmaticStreamSerializationAllowed = 1;
    cfg.attrs = at;
    cfg.numAttrs = 1;
    cudaLaunchKernelEx(&cfg, kern, args...);
}

extern "C" void kernel_launch(void* const* d_in, const int* in_sizes, int n_in,
                              void* d_out, int out_size)
{
    const float* x     = (const float*)d_in[0];
    const float* W1    = (const float*)d_in[1];
    const float* b1    = (const float*)d_in[2];
    const float* W2    = (const float*)d_in[3];
    const float* b2    = (const float*)d_in[4];
    const float* W_exp = (const float*)d_in[5];
    const float* b_exp = (const float*)d_in[6];
    const float* W_v   = (const float*)d_in[7];
    const float* b_v   = (const float*)d_in[8];
    const float* W_k   = (const float*)d_in[9];
    const float* b_k   = (const float*)d_in[10];
    const float* W_q   = (const float*)d_in[11];
    const float* b_q   = (const float*)d_in[12];
    const float* W_t   = (const float*)d_in[13];
    const float* b_t   = (const float*)d_in[14];
    const float* W_l   = (const float*)d_in[15];
    const float* b_l   = (const float*)d_in[16];
    const int*   tid   = (const int*)d_in[17];
    float* out = (float*)d_out;

    float *pA, *pB, *pC, *pDs, *pE, *pF, *pG;
    cudaGetSymbolAddress((void**)&pA, g_pA);
    cudaGetSymbolAddress((void**)&pB, g_pB);
    cudaGetSymbolAddress((void**)&pC, g_pC);
    cudaGetSymbolAddress((void**)&pDs, g_pDs);
    cudaGetSymbolAddress((void**)&pE, g_pE);
    cudaGetSymbolAddress((void**)&pF, g_pF);
    cudaGetSymbolAddress((void**)&pG, g_pG);

    // A: pA = splitK(x @ W1)             16MB, full register prefetch
    launch_pdl(gemv_k<256, 16, 2048, 1, 0, 0, 1, false, false, 16>,
               dim3(2, 128, 1), dim3(256), W1, x, (const float*)nullptr, pA);
    // B: h1 fused; pB = splitK(h1 @ W2)   16MB
    launch_pdl(gemv_k<256, 16, 2048, 1, 1, 128, 2048, true, false, 16>,
               dim3(2, 128, 1), dim3(256), W2, pA, b1, pB);
    // C: h2 fused; pC[n] = splitK(h2 @ W_exp[n])   256MB, 1024 blocks
    launch_pdl(gemv_k<256, 64, 2048, 1, 1, 128, 2048, true, false, 0>,
               dim3(2, 32, 16), dim3(256), W_exp, pB, b2, pC);
    // D+E merged + in-kernel k.q dot      288MB, uniform 1024 blocks
    launch_pdl(gemv_DE, dim3(2, 32, 16), dim3(256),
               W_v, W_k, pC, b_exp, W_q, b_q, tid, pE, pDs);
    // F: ekq reconstructed in-prologue; res fused; pF = splitK(res @ W_t)  16MB
    launch_pdl(gemv_F, dim3(2, 128, 1), dim3(256),
               W_t, pE, pDs, b_k, W_q, b_q, b_v, tid, pF);
    // G: t fused; pG = splitK(t @ W_l)    4MB
    launch_pdl(gemv_k<256, 16, 512, 2, 1, 128, 2048, true, false, 8>,
               dim3(1, 128, 1), dim3(256), W_l, pF, b_t, pG);
    // out
    launch_pdl(fin_out, dim3(8), dim3(256), pG, b_l, out);
}